// round 9
// baseline (speedup 1.0000x reference)
#include <cuda_runtime.h>
#include <cuda_fp16.h>
#include <cstdint>

typedef uint32_t u32;

static constexpr int NB = 32, NN = 128, DD = 64;

// Precomputed A-transpose fp16 image: At[j][k] = A[b][k][j],
// 128 rows, row stride 136 fp16 (272B), 128 valid k + pad.
__device__ __align__(16) unsigned char g_Ah[32][34816];

// ---------------- helpers ----------------
__device__ __forceinline__ u32 smem_u32(const void* p) {
    u32 a;
    asm("{ .reg .u64 t; cvta.to.shared.u64 t, %1; cvt.u32.u64 %0, t; }" : "=r"(a) : "l"(p));
    return a;
}
__device__ __forceinline__ u32 pack_h16(float lo, float hi) {
    u32 r;
    asm("cvt.rn.f16x2.f32 %0, %1, %2;" : "=r"(r) : "f"(hi), "f"(lo));
    return r;
}
__device__ __forceinline__ void sts32(u32 a, u32 v) {
    asm volatile("st.shared.b32 [%0], %1;" :: "r"(a), "r"(v) : "memory");
}
__device__ __forceinline__ void sts64(u32 a, u32 x, u32 y) {
    asm volatile("st.shared.v2.b32 [%0], {%1,%2};" :: "r"(a), "r"(x), "r"(y) : "memory");
}
__device__ __forceinline__ void sts128(u32 a, u32 x, u32 y, u32 z, u32 w) {
    asm volatile("st.shared.v4.b32 [%0], {%1,%2,%3,%4};" :: "r"(a), "r"(x), "r"(y), "r"(z), "r"(w) : "memory");
}
__device__ __forceinline__ void lds64f(float& x, float& y, u32 a) {
    asm volatile("ld.shared.v2.f32 {%0,%1}, [%2];" : "=f"(x), "=f"(y) : "r"(a));
}
__device__ __forceinline__ void ldsm4(u32* f, u32 a) {
    asm volatile("ldmatrix.sync.aligned.m8n8.x4.shared.b16 {%0,%1,%2,%3}, [%4];"
                 : "=r"(f[0]), "=r"(f[1]), "=r"(f[2]), "=r"(f[3]) : "r"(a));
}
__device__ __forceinline__ void ldsm4t(u32* f, u32 a) {
    asm volatile("ldmatrix.sync.aligned.m8n8.x4.trans.shared.b16 {%0,%1,%2,%3}, [%4];"
                 : "=r"(f[0]), "=r"(f[1]), "=r"(f[2]), "=r"(f[3]) : "r"(a));
}
__device__ __forceinline__ void mma_f16(float* c, const u32* a, const u32* b) {
    asm volatile(
        "mma.sync.aligned.m16n8k16.row.col.f32.f16.f16.f32 "
        "{%0,%1,%2,%3}, {%4,%5,%6,%7}, {%8,%9}, {%0,%1,%2,%3};"
        : "+f"(c[0]), "+f"(c[1]), "+f"(c[2]), "+f"(c[3])
        : "r"(a[0]), "r"(a[1]), "r"(a[2]), "r"(a[3]), "r"(b[0]), "r"(b[1]));
}

// ---------------- smem layout ----------------
static constexpr u32 RS64  = 144;   // 64-wide fp16 tile row stride (bytes)
static constexpr u32 RS128 = 272;   // 128-wide tile row stride

static constexpr u32 OFF_W1  = 0;        // 9216
static constexpr u32 OFF_W2  = 9216;     // 9216
static constexpr u32 OFF_AT  = 18432;    // 34816
static constexpr u32 OFF_XH2 = 53248;    // 18432 (X, then h2 overlay)
static constexpr u32 OFF_B1  = 71680;    // 256
static constexpr u32 OFF_B2  = 71936;    // 256
static constexpr u32 SMEM_BYTES = 72192; // -> 3 CTAs/SM

static constexpr int I_PER_CTA = 2;

// =============== prep: A[b][k][j] -> At fp16 image ===============
__global__ void prep_At(const float* __restrict__ A)
{
    __shared__ float tile[32][33];
    const int b = blockIdx.z, k0 = blockIdx.x * 32, j0 = blockIdx.y * 32;
    const int tx = threadIdx.x & 31, ty = threadIdx.x >> 5;   // ty: 0..7

    const float* Ab = A + ((size_t)b * NN + k0) * NN + j0;
    #pragma unroll
    for (int s = 0; s < 4; ++s)
        tile[ty + 8 * s][tx] = Ab[(ty + 8 * s) * NN + tx];
    __syncthreads();

    const int j  = threadIdx.x >> 3;   // 0..31
    const int kq = threadIdx.x & 7;    // 4 k values each
    float v[4];
    #pragma unroll
    for (int s = 0; s < 4; ++s) v[s] = tile[kq * 4 + s][j];

    uint2 h = make_uint2(pack_h16(v[0], v[1]), pack_h16(v[2], v[3]));
    size_t off = (size_t)(j0 + j) * RS128 + (size_t)(k0 + kq * 4) * 2;
    *reinterpret_cast<uint2*>(&g_Ah[b][off]) = h;
}

// =============== main fused kernel ===============
__global__ __launch_bounds__(256, 3)
void crosssubg_mma_kernel(const float* __restrict__ X,
                          const float* __restrict__ W1,
                          const float* __restrict__ b1,
                          const float* __restrict__ W2,
                          const float* __restrict__ b2,
                          float* __restrict__ out)
{
    extern __shared__ __align__(256) unsigned char smraw[];
    const u32 sb = smem_u32(smraw);

    const int ig   = blockIdx.x;            // i-group (0..63)
    const int b    = blockIdx.y;            // batch
    const int tid  = (int)threadIdx.x;
    const int wid  = tid >> 5;
    const int lane = tid & 31;
    const int row0 = wid * 16;              // G1/G2 m-rows
    const int wm   = wid >> 1, wn = wid & 1;
    const int j0   = wm * 32, d0 = wn * 32; // G3 warp tile origin
    const int fr   = lane >> 2, fc = lane & 3;

    // ---- one-time staging: W1, W2, At, biases ----
    {
        const float4* gW1 = (const float4*)W1;   // 1024 each
        const float4* gW2 = (const float4*)W2;
        #pragma unroll
        for (int it = 0; it < 8; ++it) {
            int t = tid + it * 256;              // 0..2047
            int sel = t >> 10;
            int r = t & 1023;
            float4 v = sel ? gW2[r] : gW1[r];
            int d = r >> 4, e0 = (r & 15) * 4;
            sts64(sb + (sel ? OFF_W2 : OFF_W1) + (u32)d * RS64 + (u32)e0 * 2,
                  pack_h16(v.x, v.y), pack_h16(v.z, v.w));
        }
        const uint4* gA = (const uint4*)&g_Ah[b][0];   // 2176 uint4
        #pragma unroll
        for (int it = 0; it < 9; ++it) {
            int t = tid + it * 256;
            if (t < 2176) {
                uint4 v = gA[t];
                sts128(sb + OFF_AT + (u32)t * 16, v.x, v.y, v.z, v.w);
            }
        }
        if (tid < 64)       sts32(sb + OFF_B1 + (u32)tid * 4, __float_as_uint(__ldg(&b1[tid])));
        else if (tid < 128) sts32(sb + OFF_B2 + (u32)(tid - 64) * 4, __float_as_uint(__ldg(&b2[tid - 64])));
    }

    // precomputed addresses
    const u32 aoffX = sb + OFF_XH2 + ((u32)row0 + (u32)(lane & 15)) * RS64 + (u32)(lane >> 4) * 16;
    const u32 boffW = (u32)(lane & 15) * RS64 + (u32)(lane >> 4) * 16;
    const u32 aoffA = sb + OFF_AT + ((u32)j0 + (u32)(lane & 15)) * RS128 + (u32)(lane >> 4) * 16;
    const u32 boffH = sb + OFF_XH2 + (u32)(lane & 15) * RS64 + (u32)d0 * 2 + (u32)(lane >> 4) * 16;

    for (int t2 = 0; t2 < I_PER_CTA; ++t2) {
        const size_t tile = (size_t)(b * NN + ig * I_PER_CTA + t2);

        __syncthreads();   // bar0: W/At staged (t=0); G3(t-1) h2 readers done -> region reusable

        // ---- stage X (fp16, coalesced float4) into XH2 region ----
        {
            const float4* gX4 = (const float4*)(X + tile * (NN * DD));  // 2048 float4
            #pragma unroll
            for (int it = 0; it < 8; ++it) {
                int t = tid + it * 256;
                float4 v = gX4[t];
                int k = t >> 4, dq = (t & 15) * 4;
                sts64(sb + OFF_XH2 + (u32)k * RS64 + (u32)dq * 2,
                      pack_h16(v.x, v.y), pack_h16(v.z, v.w));
            }
        }
        __syncthreads();   // bar1: X visible

        // ---- GEMM1: acc1 = X W1  (M=128 N=64 K=64) ----
        float acc1[8][4];
        #pragma unroll
        for (int n = 0; n < 8; ++n)
            #pragma unroll
            for (int q = 0; q < 4; ++q) acc1[n][q] = 0.0f;
        #pragma unroll
        for (int ks = 0; ks < 4; ++ks) {
            u32 fa[4];
            ldsm4(fa, aoffX + (u32)ks * 32);
            const u32 bb = sb + OFF_W1 + (u32)ks * 16 * RS64 + boffW;
            #pragma unroll
            for (int np = 0; np < 4; ++np) {
                u32 fb[4];
                ldsm4t(fb, bb + (u32)np * 32);
                mma_f16(acc1[2 * np],     fa, fb);
                mma_f16(acc1[2 * np + 1], fa, fb + 2);
            }
        }

        // ---- GEMM2: acc2 = relu(acc1 + b1) W2, A-fragments built in registers ----
        float acc2[8][4];
        #pragma unroll
        for (int n = 0; n < 8; ++n)
            #pragma unroll
            for (int q = 0; q < 4; ++q) acc2[n][q] = 0.0f;
        #pragma unroll
        for (int ks = 0; ks < 4; ++ks) {
            float bz0, bz1, bz2, bz3;
            lds64f(bz0, bz1, sb + OFF_B1 + (u32)(16 * ks + 2 * fc) * 4);
            lds64f(bz2, bz3, sb + OFF_B1 + (u32)(16 * ks + 8 + 2 * fc) * 4);
            u32 fa[4];
            fa[0] = pack_h16(fmaxf(acc1[2 * ks][0] + bz0, 0.f), fmaxf(acc1[2 * ks][1] + bz1, 0.f));
            fa[1] = pack_h16(fmaxf(acc1[2 * ks][2] + bz0, 0.f), fmaxf(acc1[2 * ks][3] + bz1, 0.f));
            fa[2] = pack_h16(fmaxf(acc1[2 * ks + 1][0] + bz2, 0.f), fmaxf(acc1[2 * ks + 1][1] + bz3, 0.f));
            fa[3] = pack_h16(fmaxf(acc1[2 * ks + 1][2] + bz2, 0.f), fmaxf(acc1[2 * ks + 1][3] + bz3, 0.f));
            const u32 bb = sb + OFF_W2 + (u32)ks * 16 * RS64 + boffW;
            #pragma unroll
            for (int np = 0; np < 4; ++np) {
                u32 fb[4];
                ldsm4t(fb, bb + (u32)np * 32);
                mma_f16(acc2[2 * np],     fa, fb);
                mma_f16(acc2[2 * np + 1], fa, fb + 2);
            }
        }

        __syncthreads();   // bar2: all warps' G1 reads of X done -> overlay safe

        // ---- h2 = relu(acc2 + b2) -> smem fp16 (overwrites X region) ----
        {
            const int r  = row0 + fr;
            const int cb = 2 * fc;
            #pragma unroll
            for (int n0 = 0; n0 < 8; ++n0) {
                const int col = n0 * 8 + cb;
                float bz0, bz1;
                lds64f(bz0, bz1, sb + OFF_B2 + (u32)col * 4);
                float v0 = fmaxf(acc2[n0][0] + bz0, 0.f);
                float v1 = fmaxf(acc2[n0][1] + bz1, 0.f);
                float v2 = fmaxf(acc2[n0][2] + bz0, 0.f);
                float v3 = fmaxf(acc2[n0][3] + bz1, 0.f);
                const u32 a0 = sb + OFF_XH2 + (u32)r * RS64 + (u32)col * 2;
                sts32(a0,             pack_h16(v0, v1));
                sts32(a0 + 8u * RS64, pack_h16(v2, v3));
            }
        }
        __syncthreads();   // bar3: h2 visible

        // ---- GEMM3: out[j][d] = sum_k At[j][k] h2[k][d]  (warp tile 32x32) ----
        float acc3[8][4];
        #pragma unroll
        for (int n = 0; n < 8; ++n)
            #pragma unroll
            for (int q = 0; q < 4; ++q) acc3[n][q] = 0.0f;
        #pragma unroll
        for (int ks = 0; ks < 8; ++ks) {
            u32 fa0[4], fa1[4], fb0[4], fb1[4];
            ldsm4(fa0, aoffA + (u32)ks * 32);
            ldsm4(fa1, aoffA + 16u * RS128 + (u32)ks * 32);
            const u32 bb = boffH + (u32)ks * 16 * RS64;
            ldsm4t(fb0, bb);
            ldsm4t(fb1, bb + 32);
            mma_f16(acc3[0], fa0, fb0); mma_f16(acc3[1], fa0, fb0 + 2);
            mma_f16(acc3[2], fa0, fb1); mma_f16(acc3[3], fa0, fb1 + 2);
            mma_f16(acc3[4], fa1, fb0); mma_f16(acc3[5], fa1, fb0 + 2);
            mma_f16(acc3[6], fa1, fb1); mma_f16(acc3[7], fa1, fb1 + 2);
        }

        // ---- store to global ----
        {
            float* gO = out + tile * (NN * DD);
            const int cb = 2 * fc;
            #pragma unroll
            for (int mb = 0; mb < 2; ++mb) {
                const int j = j0 + 16 * mb + fr;
                #pragma unroll
                for (int nb = 0; nb < 4; ++nb) {
                    const float* a = acc3[mb * 4 + nb];
                    const int col = d0 + 8 * nb + cb;
                    *(float2*)(gO + (size_t)j * DD + col)       = make_float2(a[0], a[1]);
                    *(float2*)(gO + (size_t)(j + 8) * DD + col) = make_float2(a[2], a[3]);
                }
            }
        }
    }
}

extern "C" void kernel_launch(void* const* d_in, const int* in_sizes, int n_in,
                              void* d_out, int out_size)
{
    const float *X = nullptr, *A = nullptr, *W1 = nullptr, *b1 = nullptr,
                *W2 = nullptr, *b2 = nullptr;
    for (int idx = 0; idx < n_in; ++idx) {
        const float* p = (const float*)d_in[idx];
        int s = in_sizes[idx];
        if      (s == NB * NN * NN * DD) X = p;
        else if (s == NB * NN * NN)      A = p;
        else if (s == DD * DD)           { if (!W1) W1 = p; else W2 = p; }
        else if (s == DD)                { if (!b1) b1 = p; else b2 = p; }
    }

    prep_At<<<dim3(4, 4, 32), 256>>>(A);

    cudaFuncSetAttribute(crosssubg_mma_kernel,
                         cudaFuncAttributeMaxDynamicSharedMemorySize, SMEM_BYTES);
    dim3 grid(NN / I_PER_CTA, NB);   // (64, 32)
    crosssubg_mma_kernel<<<grid, 256, SMEM_BYTES>>>(X, W1, b1, W2, b2, (float*)d_out);
}

// round 10
// speedup vs baseline: 1.0003x; 1.0003x over previous
#include <cuda_runtime.h>
#include <cuda_fp16.h>
#include <cstdint>

typedef uint32_t u32;

static constexpr int NB = 32, NN = 128, DD = 64;
static constexpr int NCTA = 444;           // 148 SMs x 3 resident CTAs
static constexpr int NTILES = NB * NN;     // 4096

// Precomputed A-transpose fp16 image: At[j][k] = A[b][k][j],
// 128 rows, row stride 136 fp16 (272B), 128 valid k + pad.
__device__ __align__(16) unsigned char g_Ah[32][34816];

// ---------------- helpers ----------------
__device__ __forceinline__ u32 smem_u32(const void* p) {
    u32 a;
    asm("{ .reg .u64 t; cvta.to.shared.u64 t, %1; cvt.u32.u64 %0, t; }" : "=r"(a) : "l"(p));
    return a;
}
__device__ __forceinline__ u32 pack_h16(float lo, float hi) {
    u32 r;
    asm("cvt.rn.f16x2.f32 %0, %1, %2;" : "=r"(r) : "f"(hi), "f"(lo));
    return r;
}
__device__ __forceinline__ void sts32(u32 a, u32 v) {
    asm volatile("st.shared.b32 [%0], %1;" :: "r"(a), "r"(v) : "memory");
}
__device__ __forceinline__ void sts64(u32 a, u32 x, u32 y) {
    asm volatile("st.shared.v2.b32 [%0], {%1,%2};" :: "r"(a), "r"(x), "r"(y) : "memory");
}
__device__ __forceinline__ void sts128(u32 a, u32 x, u32 y, u32 z, u32 w) {
    asm volatile("st.shared.v4.b32 [%0], {%1,%2,%3,%4};" :: "r"(a), "r"(x), "r"(y), "r"(z), "r"(w) : "memory");
}
__device__ __forceinline__ void lds64f(float& x, float& y, u32 a) {
    asm volatile("ld.shared.v2.f32 {%0,%1}, [%2];" : "=f"(x), "=f"(y) : "r"(a));
}
__device__ __forceinline__ void ldsm4(u32* f, u32 a) {
    asm volatile("ldmatrix.sync.aligned.m8n8.x4.shared.b16 {%0,%1,%2,%3}, [%4];"
                 : "=r"(f[0]), "=r"(f[1]), "=r"(f[2]), "=r"(f[3]) : "r"(a));
}
__device__ __forceinline__ void ldsm4t(u32* f, u32 a) {
    asm volatile("ldmatrix.sync.aligned.m8n8.x4.trans.shared.b16 {%0,%1,%2,%3}, [%4];"
                 : "=r"(f[0]), "=r"(f[1]), "=r"(f[2]), "=r"(f[3]) : "r"(a));
}
__device__ __forceinline__ void mma_f16(float* c, const u32* a, const u32* b) {
    asm volatile(
        "mma.sync.aligned.m16n8k16.row.col.f32.f16.f16.f32 "
        "{%0,%1,%2,%3}, {%4,%5,%6,%7}, {%8,%9}, {%0,%1,%2,%3};"
        : "+f"(c[0]), "+f"(c[1]), "+f"(c[2]), "+f"(c[3])
        : "r"(a[0]), "r"(a[1]), "r"(a[2]), "r"(a[3]), "r"(b[0]), "r"(b[1]));
}

// ---------------- smem layout ----------------
static constexpr u32 RS64  = 144;   // 64-wide fp16 tile row stride (bytes)
static constexpr u32 RS128 = 272;   // 128-wide tile row stride

static constexpr u32 OFF_W1  = 0;        // 9216
static constexpr u32 OFF_W2  = 9216;     // 9216
static constexpr u32 OFF_AT  = 18432;    // 34816
static constexpr u32 OFF_XH2 = 53248;    // 18432 (X, then h2 overlay)
static constexpr u32 OFF_B1  = 71680;    // 256
static constexpr u32 OFF_B2  = 71936;    // 256
static constexpr u32 SMEM_BYTES = 72192; // -> 3 CTAs/SM

// =============== prep: A[b][k][j] -> At fp16 image ===============
__global__ void prep_At(const float* __restrict__ A)
{
    __shared__ float tile[32][33];
    const int b = blockIdx.z, k0 = blockIdx.x * 32, j0 = blockIdx.y * 32;
    const int tx = threadIdx.x & 31, ty = threadIdx.x >> 5;   // ty: 0..7

    const float* Ab = A + ((size_t)b * NN + k0) * NN + j0;
    #pragma unroll
    for (int s = 0; s < 4; ++s)
        tile[ty + 8 * s][tx] = Ab[(ty + 8 * s) * NN + tx];
    __syncthreads();

    const int j  = threadIdx.x >> 3;   // 0..31
    const int kq = threadIdx.x & 7;    // 4 k values each
    float v[4];
    #pragma unroll
    for (int s = 0; s < 4; ++s) v[s] = tile[kq * 4 + s][j];

    uint2 h = make_uint2(pack_h16(v[0], v[1]), pack_h16(v[2], v[3]));
    size_t off = (size_t)(j0 + j) * RS128 + (size_t)(k0 + kq * 4) * 2;
    *reinterpret_cast<uint2*>(&g_Ah[b][off]) = h;
}

// =============== main fused persistent kernel ===============
__global__ __launch_bounds__(256, 3)
void crosssubg_mma_kernel(const float* __restrict__ X,
                          const float* __restrict__ W1,
                          const float* __restrict__ b1,
                          const float* __restrict__ W2,
                          const float* __restrict__ b2,
                          float* __restrict__ out)
{
    extern __shared__ __align__(256) unsigned char smraw[];
    const u32 sb = smem_u32(smraw);

    const int cta  = blockIdx.x;
    const int tid  = (int)threadIdx.x;
    const int wid  = tid >> 5;
    const int lane = tid & 31;
    const int row0 = wid * 16;              // G1/G2 m-rows
    const int wm   = wid >> 1, wn = wid & 1;
    const int j0   = wm * 32, d0 = wn * 32; // G3 warp tile origin
    const int fr   = lane >> 2, fc = lane & 3;

    const int t_begin = (cta * NTILES) / NCTA;
    const int t_end   = ((cta + 1) * NTILES) / NCTA;

    // ---- one-time staging: W1, W2, biases ----
    {
        const float4* gW1 = (const float4*)W1;   // 1024 each
        const float4* gW2 = (const float4*)W2;
        #pragma unroll
        for (int it = 0; it < 8; ++it) {
            int t = tid + it * 256;              // 0..2047
            int sel = t >> 10;
            int r = t & 1023;
            float4 v = sel ? gW2[r] : gW1[r];
            int d = r >> 4, e0 = (r & 15) * 4;
            sts64(sb + (sel ? OFF_W2 : OFF_W1) + (u32)d * RS64 + (u32)e0 * 2,
                  pack_h16(v.x, v.y), pack_h16(v.z, v.w));
        }
        if (tid < 64)       sts32(sb + OFF_B1 + (u32)tid * 4, __float_as_uint(__ldg(&b1[tid])));
        else if (tid < 128) sts32(sb + OFF_B2 + (u32)(tid - 64) * 4, __float_as_uint(__ldg(&b2[tid - 64])));
    }

    // precomputed addresses
    const u32 aoffX = sb + OFF_XH2 + ((u32)row0 + (u32)(lane & 15)) * RS64 + (u32)(lane >> 4) * 16;
    const u32 boffW = (u32)(lane & 15) * RS64 + (u32)(lane >> 4) * 16;
    const u32 aoffA = sb + OFF_AT + ((u32)j0 + (u32)(lane & 15)) * RS128 + (u32)(lane >> 4) * 16;
    const u32 boffH = sb + OFF_XH2 + (u32)(lane & 15) * RS64 + (u32)d0 * 2 + (u32)(lane >> 4) * 16;

    int cur_b = -1;

    for (int t = t_begin; t < t_end; ++t) {
        const int b = t >> 7;   // tile / 128

        __syncthreads();   // bar0: W staged / G3(t-1) h2+At readers done

        // ---- re-stage At on batch change (<=2x per CTA) ----
        if (b != cur_b) {
            cur_b = b;
            const uint4* gA = (const uint4*)&g_Ah[b][0];   // 2176 uint4
            #pragma unroll
            for (int it = 0; it < 9; ++it) {
                int q = tid + it * 256;
                if (q < 2176) {
                    uint4 v = gA[q];
                    sts128(sb + OFF_AT + (u32)q * 16, v.x, v.y, v.z, v.w);
                }
            }
        }

        // ---- stage X (fp16, coalesced float4) into XH2 region ----
        {
            const float4* gX4 = (const float4*)(X + (size_t)t * (NN * DD));  // 2048 float4
            #pragma unroll
            for (int it = 0; it < 8; ++it) {
                int q = tid + it * 256;
                float4 v = gX4[q];
                int k = q >> 4, dq = (q & 15) * 4;
                sts64(sb + OFF_XH2 + (u32)k * RS64 + (u32)dq * 2,
                      pack_h16(v.x, v.y), pack_h16(v.z, v.w));
            }
        }
        __syncthreads();   // bar1: X (and At) visible

        // ---- GEMM1: acc1 = X W1  (M=128 N=64 K=64) ----
        float acc1[8][4];
        #pragma unroll
        for (int n = 0; n < 8; ++n)
            #pragma unroll
            for (int q = 0; q < 4; ++q) acc1[n][q] = 0.0f;
        #pragma unroll
        for (int ks = 0; ks < 4; ++ks) {
            u32 fa[4];
            ldsm4(fa, aoffX + (u32)ks * 32);
            const u32 bb = sb + OFF_W1 + (u32)ks * 16 * RS64 + boffW;
            #pragma unroll
            for (int np = 0; np < 4; ++np) {
                u32 fb[4];
                ldsm4t(fb, bb + (u32)np * 32);
                mma_f16(acc1[2 * np],     fa, fb);
                mma_f16(acc1[2 * np + 1], fa, fb + 2);
            }
        }

        // ---- GEMM2: acc2 = relu(acc1 + b1) W2, A-fragments built in registers ----
        float acc2[8][4];
        #pragma unroll
        for (int n = 0; n < 8; ++n)
            #pragma unroll
            for (int q = 0; q < 4; ++q) acc2[n][q] = 0.0f;
        #pragma unroll
        for (int ks = 0; ks < 4; ++ks) {
            float bz0, bz1, bz2, bz3;
            lds64f(bz0, bz1, sb + OFF_B1 + (u32)(16 * ks + 2 * fc) * 4);
            lds64f(bz2, bz3, sb + OFF_B1 + (u32)(16 * ks + 8 + 2 * fc) * 4);
            u32 fa[4];
            fa[0] = pack_h16(fmaxf(acc1[2 * ks][0] + bz0, 0.f), fmaxf(acc1[2 * ks][1] + bz1, 0.f));
            fa[1] = pack_h16(fmaxf(acc1[2 * ks][2] + bz0, 0.f), fmaxf(acc1[2 * ks][3] + bz1, 0.f));
            fa[2] = pack_h16(fmaxf(acc1[2 * ks + 1][0] + bz2, 0.f), fmaxf(acc1[2 * ks + 1][1] + bz3, 0.f));
            fa[3] = pack_h16(fmaxf(acc1[2 * ks + 1][2] + bz2, 0.f), fmaxf(acc1[2 * ks + 1][3] + bz3, 0.f));
            const u32 bb = sb + OFF_W2 + (u32)ks * 16 * RS64 + boffW;
            #pragma unroll
            for (int np = 0; np < 4; ++np) {
                u32 fb[4];
                ldsm4t(fb, bb + (u32)np * 32);
                mma_f16(acc2[2 * np],     fa, fb);
                mma_f16(acc2[2 * np + 1], fa, fb + 2);
            }
        }

        __syncthreads();   // bar2: all warps' G1 reads of X done -> overlay safe

        // ---- h2 = relu(acc2 + b2) -> smem fp16 (overwrites X region) ----
        {
            const int r  = row0 + fr;
            const int cb = 2 * fc;
            #pragma unroll
            for (int n0 = 0; n0 < 8; ++n0) {
                const int col = n0 * 8 + cb;
                float bz0, bz1;
                lds64f(bz0, bz1, sb + OFF_B2 + (u32)col * 4);
                float v0 = fmaxf(acc2[n0][0] + bz0, 0.f);
                float v1 = fmaxf(acc2[n0][1] + bz1, 0.f);
                float v2 = fmaxf(acc2[n0][2] + bz0, 0.f);
                float v3 = fmaxf(acc2[n0][3] + bz1, 0.f);
                const u32 a0 = sb + OFF_XH2 + (u32)r * RS64 + (u32)col * 2;
                sts32(a0,             pack_h16(v0, v1));
                sts32(a0 + 8u * RS64, pack_h16(v2, v3));
            }
        }
        __syncthreads();   // bar3: h2 visible

        // ---- GEMM3: out[j][d] = sum_k At[j][k] h2[k][d]  (warp tile 32x32) ----
        float acc3[8][4];
        #pragma unroll
        for (int n = 0; n < 8; ++n)
            #pragma unroll
            for (int q = 0; q < 4; ++q) acc3[n][q] = 0.0f;
        #pragma unroll
        for (int ks = 0; ks < 8; ++ks) {
            u32 fa0[4], fa1[4], fb0[4], fb1[4];
            ldsm4(fa0, aoffA + (u32)ks * 32);
            ldsm4(fa1, aoffA + 16u * RS128 + (u32)ks * 32);
            const u32 bb = boffH + (u32)ks * 16 * RS64;
            ldsm4t(fb0, bb);
            ldsm4t(fb1, bb + 32);
            mma_f16(acc3[0], fa0, fb0); mma_f16(acc3[1], fa0, fb0 + 2);
            mma_f16(acc3[2], fa0, fb1); mma_f16(acc3[3], fa0, fb1 + 2);
            mma_f16(acc3[4], fa1, fb0); mma_f16(acc3[5], fa1, fb0 + 2);
            mma_f16(acc3[6], fa1, fb1); mma_f16(acc3[7], fa1, fb1 + 2);
        }

        // ---- store to global ----
        {
            float* gO = out + (size_t)t * (NN * DD);
            const int cb = 2 * fc;
            #pragma unroll
            for (int mb = 0; mb < 2; ++mb) {
                const int j = j0 + 16 * mb + fr;
                #pragma unroll
                for (int nb = 0; nb < 4; ++nb) {
                    const float* a = acc3[mb * 4 + nb];
                    const int col = d0 + 8 * nb + cb;
                    *(float2*)(gO + (size_t)j * DD + col)       = make_float2(a[0], a[1]);
                    *(float2*)(gO + (size_t)(j + 8) * DD + col) = make_float2(a[2], a[3]);
                }
            }
        }
    }
}

extern "C" void kernel_launch(void* const* d_in, const int* in_sizes, int n_in,
                              void* d_out, int out_size)
{
    const float *X = nullptr, *A = nullptr, *W1 = nullptr, *b1 = nullptr,
                *W2 = nullptr, *b2 = nullptr;
    for (int idx = 0; idx < n_in; ++idx) {
        const float* p = (const float*)d_in[idx];
        int s = in_sizes[idx];
        if      (s == NB * NN * NN * DD) X = p;
        else if (s == NB * NN * NN)      A = p;
        else if (s == DD * DD)           { if (!W1) W1 = p; else W2 = p; }
        else if (s == DD)                { if (!b1) b1 = p; else b2 = p; }
    }

    prep_At<<<dim3(4, 4, 32), 256>>>(A);

    cudaFuncSetAttribute(crosssubg_mma_kernel,
                         cudaFuncAttributeMaxDynamicSharedMemorySize, SMEM_BYTES);
    crosssubg_mma_kernel<<<NCTA, 256, SMEM_BYTES>>>(X, W1, b1, W2, b2, (float*)d_out);
}

// round 11
// speedup vs baseline: 1.1670x; 1.1667x over previous
#include <cuda_runtime.h>
#include <cuda_fp16.h>
#include <cstdint>

typedef uint32_t u32;

static constexpr int NB = 32, NN = 128, DD = 64;
static constexpr int NCTA = 296;           // 148 SMs x 2 resident CTAs -> single wave
static constexpr int NTILES = NB * NN;     // 4096

// Precomputed A-transpose fp16 image: At[j][k] = A[b][k][j],
// 128 rows, row stride 136 fp16 (272B), 128 valid k + pad.
__device__ __align__(16) unsigned char g_Ah[32][34816];

// ---------------- helpers ----------------
__device__ __forceinline__ u32 smem_u32(const void* p) {
    u32 a;
    asm("{ .reg .u64 t; cvta.to.shared.u64 t, %1; cvt.u32.u64 %0, t; }" : "=r"(a) : "l"(p));
    return a;
}
__device__ __forceinline__ u32 pack_h16(float lo, float hi) {
    u32 r;
    asm("cvt.rn.f16x2.f32 %0, %1, %2;" : "=r"(r) : "f"(hi), "f"(lo));
    return r;
}
__device__ __forceinline__ void sts32(u32 a, u32 v) {
    asm volatile("st.shared.b32 [%0], %1;" :: "r"(a), "r"(v) : "memory");
}
__device__ __forceinline__ void sts64(u32 a, u32 x, u32 y) {
    asm volatile("st.shared.v2.b32 [%0], {%1,%2};" :: "r"(a), "r"(x), "r"(y) : "memory");
}
__device__ __forceinline__ void sts128(u32 a, u32 x, u32 y, u32 z, u32 w) {
    asm volatile("st.shared.v4.b32 [%0], {%1,%2,%3,%4};" :: "r"(a), "r"(x), "r"(y), "r"(z), "r"(w) : "memory");
}
__device__ __forceinline__ void lds64f(float& x, float& y, u32 a) {
    asm volatile("ld.shared.v2.f32 {%0,%1}, [%2];" : "=f"(x), "=f"(y) : "r"(a));
}
__device__ __forceinline__ void ldsm4(u32* f, u32 a) {
    asm volatile("ldmatrix.sync.aligned.m8n8.x4.shared.b16 {%0,%1,%2,%3}, [%4];"
                 : "=r"(f[0]), "=r"(f[1]), "=r"(f[2]), "=r"(f[3]) : "r"(a));
}
__device__ __forceinline__ void ldsm4t(u32* f, u32 a) {
    asm volatile("ldmatrix.sync.aligned.m8n8.x4.trans.shared.b16 {%0,%1,%2,%3}, [%4];"
                 : "=r"(f[0]), "=r"(f[1]), "=r"(f[2]), "=r"(f[3]) : "r"(a));
}
__device__ __forceinline__ void mma_f16(float* c, const u32* a, const u32* b) {
    asm volatile(
        "mma.sync.aligned.m16n8k16.row.col.f32.f16.f16.f32 "
        "{%0,%1,%2,%3}, {%4,%5,%6,%7}, {%8,%9}, {%0,%1,%2,%3};"
        : "+f"(c[0]), "+f"(c[1]), "+f"(c[2]), "+f"(c[3])
        : "r"(a[0]), "r"(a[1]), "r"(a[2]), "r"(a[3]), "r"(b[0]), "r"(b[1]));
}

// ---------------- smem layout (identical to the 94.3us R6 kernel) ----------------
static constexpr u32 RS64  = 144;   // 64-wide fp16 tile row stride (bytes)
static constexpr u32 RS128 = 272;   // 128-wide tile row stride

static constexpr u32 OFF_X  = 0;        // 18432
static constexpr u32 OFF_W1 = 18432;    // 9216
static constexpr u32 OFF_W2 = 27648;    // 9216
static constexpr u32 OFF_AT = 36864;    // 34816
static constexpr u32 OFF_H2 = 71680;    // 18432
static constexpr u32 OFF_B1 = 90112;    // 256
static constexpr u32 OFF_B2 = 90368;    // 256
static constexpr u32 SMEM_BYTES = 90624; // -> 2 CTAs/SM

// =============== prep: A[b][k][j] -> At fp16 image ===============
__global__ void prep_At(const float* __restrict__ A)
{
    __shared__ float tile[32][33];
    const int b = blockIdx.z, k0 = blockIdx.x * 32, j0 = blockIdx.y * 32;
    const int tx = threadIdx.x & 31, ty = threadIdx.x >> 5;   // ty: 0..7

    const float* Ab = A + ((size_t)b * NN + k0) * NN + j0;
    #pragma unroll
    for (int s = 0; s < 4; ++s)
        tile[ty + 8 * s][tx] = Ab[(ty + 8 * s) * NN + tx];
    __syncthreads();

    const int j  = threadIdx.x >> 3;   // 0..31
    const int kq = threadIdx.x & 7;    // 4 k values each
    float v[4];
    #pragma unroll
    for (int s = 0; s < 4; ++s) v[s] = tile[kq * 4 + s][j];

    uint2 h = make_uint2(pack_h16(v[0], v[1]), pack_h16(v[2], v[3]));
    size_t off = (size_t)(j0 + j) * RS128 + (size_t)(k0 + kq * 4) * 2;
    *reinterpret_cast<uint2*>(&g_Ah[b][off]) = h;
}

// =============== main fused persistent kernel ===============
__global__ __launch_bounds__(256, 2)
void crosssubg_mma_kernel(const float* __restrict__ X,
                          const float* __restrict__ W1,
                          const float* __restrict__ b1,
                          const float* __restrict__ W2,
                          const float* __restrict__ b2,
                          float* __restrict__ out)
{
    extern __shared__ __align__(256) unsigned char smraw[];
    const u32 sb = smem_u32(smraw);

    const int cta  = blockIdx.x;
    const int tid  = (int)threadIdx.x;
    const int wid  = tid >> 5;
    const int lane = tid & 31;
    const int row0 = wid * 16;              // G1/G2 m-rows
    const int wm   = wid >> 1, wn = wid & 1;
    const int j0   = wm * 32, d0 = wn * 32; // G3 warp tile origin
    const int fr   = lane >> 2, fc = lane & 3;

    const int t_begin = (int)(((long long)cta * NTILES) / NCTA);
    const int t_end   = (int)(((long long)(cta + 1) * NTILES) / NCTA);

    // ---- one-time staging: W1, W2, biases ----
    {
        const float4* gW1 = (const float4*)W1;   // 1024 each
        const float4* gW2 = (const float4*)W2;
        #pragma unroll
        for (int it = 0; it < 8; ++it) {
            int t = tid + it * 256;              // 0..2047
            int sel = t >> 10;
            int r = t & 1023;
            float4 v = sel ? gW2[r] : gW1[r];
            int d = r >> 4, e0 = (r & 15) * 4;
            sts64(sb + (sel ? OFF_W2 : OFF_W1) + (u32)d * RS64 + (u32)e0 * 2,
                  pack_h16(v.x, v.y), pack_h16(v.z, v.w));
        }
        if (tid < 64)       sts32(sb + OFF_B1 + (u32)tid * 4, __float_as_uint(__ldg(&b1[tid])));
        else if (tid < 128) sts32(sb + OFF_B2 + (u32)(tid - 64) * 4, __float_as_uint(__ldg(&b2[tid - 64])));
    }

    // precomputed addresses
    const u32 aoffX = sb + OFF_X + ((u32)row0 + (u32)(lane & 15)) * RS64 + (u32)(lane >> 4) * 16;
    const u32 boffW = (u32)(lane & 15) * RS64 + (u32)(lane >> 4) * 16;
    const u32 aoffA = sb + OFF_AT + ((u32)j0 + (u32)(lane & 15)) * RS128 + (u32)(lane >> 4) * 16;
    const u32 boffH = sb + OFF_H2 + (u32)(lane & 15) * RS64 + (u32)d0 * 2 + (u32)(lane >> 4) * 16;

    int cur_b = -1;

    for (int t = t_begin; t < t_end; ++t) {
        const int b = t >> 7;   // tile / 128

        // ---- At (re)stage on batch change: <=2 per CTA; needs a barrier so no
        //      warp is still reading At in G3(t-1). ----
        if (b != cur_b) {
            __syncthreads();
            cur_b = b;
            const uint4* gA = (const uint4*)&g_Ah[b][0];   // 2176 uint4
            #pragma unroll
            for (int it = 0; it < 9; ++it) {
                int q = tid + it * 256;
                if (q < 2176) {
                    uint4 v = gA[q];
                    sts128(sb + OFF_AT + (u32)q * 16, v.x, v.y, v.z, v.w);
                }
            }
        }

        // ---- stage X (fp16, coalesced float4); X region is not read by G3(t-1) ----
        {
            const float4* gX4 = (const float4*)(X + (size_t)t * (NN * DD));  // 2048 float4
            #pragma unroll
            for (int it = 0; it < 8; ++it) {
                int q = tid + it * 256;
                float4 v = gX4[q];
                int k = q >> 4, dq = (q & 15) * 4;
                sts64(sb + OFF_X + (u32)k * RS64 + (u32)dq * 2,
                      pack_h16(v.x, v.y), pack_h16(v.z, v.w));
            }
        }
        __syncthreads();   // bar1: X (+At) visible; all warps past G3(t-1)

        // ---- GEMM1: acc1 = X W1  (M=128 N=64 K=64) ----
        float acc1[8][4];
        #pragma unroll
        for (int n = 0; n < 8; ++n)
            #pragma unroll
            for (int q = 0; q < 4; ++q) acc1[n][q] = 0.0f;
        #pragma unroll
        for (int ks = 0; ks < 4; ++ks) {
            u32 fa[4];
            ldsm4(fa, aoffX + (u32)ks * 32);
            const u32 bb = sb + OFF_W1 + (u32)ks * 16 * RS64 + boffW;
            #pragma unroll
            for (int np = 0; np < 4; ++np) {
                u32 fb[4];
                ldsm4t(fb, bb + (u32)np * 32);
                mma_f16(acc1[2 * np],     fa, fb);
                mma_f16(acc1[2 * np + 1], fa, fb + 2);
            }
        }

        // ---- GEMM2: acc2 = relu(acc1 + b1) W2, A-fragments built in registers ----
        float acc2[8][4];
        #pragma unroll
        for (int n = 0; n < 8; ++n)
            #pragma unroll
            for (int q = 0; q < 4; ++q) acc2[n][q] = 0.0f;
        #pragma unroll
        for (int ks = 0; ks < 4; ++ks) {
            float bz0, bz1, bz2, bz3;
            lds64f(bz0, bz1, sb + OFF_B1 + (u32)(16 * ks + 2 * fc) * 4);
            lds64f(bz2, bz3, sb + OFF_B1 + (u32)(16 * ks + 8 + 2 * fc) * 4);
            u32 fa[4];
            fa[0] = pack_h16(fmaxf(acc1[2 * ks][0] + bz0, 0.f), fmaxf(acc1[2 * ks][1] + bz1, 0.f));
            fa[1] = pack_h16(fmaxf(acc1[2 * ks][2] + bz0, 0.f), fmaxf(acc1[2 * ks][3] + bz1, 0.f));
            fa[2] = pack_h16(fmaxf(acc1[2 * ks + 1][0] + bz2, 0.f), fmaxf(acc1[2 * ks + 1][1] + bz3, 0.f));
            fa[3] = pack_h16(fmaxf(acc1[2 * ks + 1][2] + bz2, 0.f), fmaxf(acc1[2 * ks + 1][3] + bz3, 0.f));
            const u32 bb = sb + OFF_W2 + (u32)ks * 16 * RS64 + boffW;
            #pragma unroll
            for (int np = 0; np < 4; ++np) {
                u32 fb[4];
                ldsm4t(fb, bb + (u32)np * 32);
                mma_f16(acc2[2 * np],     fa, fb);
                mma_f16(acc2[2 * np + 1], fa, fb + 2);
            }
        }

        // ---- h2 = relu(acc2 + b2) -> smem fp16 (separate region, safe after bar1) ----
        {
            const int r  = row0 + fr;
            const int cb = 2 * fc;
            #pragma unroll
            for (int n0 = 0; n0 < 8; ++n0) {
                const int col = n0 * 8 + cb;
                float bz0, bz1;
                lds64f(bz0, bz1, sb + OFF_B2 + (u32)col * 4);
                float v0 = fmaxf(acc2[n0][0] + bz0, 0.f);
                float v1 = fmaxf(acc2[n0][1] + bz1, 0.f);
                float v2 = fmaxf(acc2[n0][2] + bz0, 0.f);
                float v3 = fmaxf(acc2[n0][3] + bz1, 0.f);
                const u32 a0 = sb + OFF_H2 + (u32)r * RS64 + (u32)col * 2;
                sts32(a0,             pack_h16(v0, v1));
                sts32(a0 + 8u * RS64, pack_h16(v2, v3));
            }
        }
        __syncthreads();   // bar2: h2 visible

        // ---- GEMM3: out[j][d] = sum_k At[j][k] h2[k][d]  (warp tile 32x32) ----
        float acc3[8][4];
        #pragma unroll
        for (int n = 0; n < 8; ++n)
            #pragma unroll
            for (int q = 0; q < 4; ++q) acc3[n][q] = 0.0f;
        #pragma unroll
        for (int ks = 0; ks < 8; ++ks) {
            u32 fa0[4], fa1[4], fb0[4], fb1[4];
            ldsm4(fa0, aoffA + (u32)ks * 32);
            ldsm4(fa1, aoffA + 16u * RS128 + (u32)ks * 32);
            const u32 bb = boffH + (u32)ks * 16 * RS64;
            ldsm4t(fb0, bb);
            ldsm4t(fb1, bb + 32);
            mma_f16(acc3[0], fa0, fb0); mma_f16(acc3[1], fa0, fb0 + 2);
            mma_f16(acc3[2], fa0, fb1); mma_f16(acc3[3], fa0, fb1 + 2);
            mma_f16(acc3[4], fa1, fb0); mma_f16(acc3[5], fa1, fb0 + 2);
            mma_f16(acc3[6], fa1, fb1); mma_f16(acc3[7], fa1, fb1 + 2);
        }

        // ---- store to global ----
        {
            float* gO = out + (size_t)t * (NN * DD);
            const int cb = 2 * fc;
            #pragma unroll
            for (int mb = 0; mb < 2; ++mb) {
                const int j = j0 + 16 * mb + fr;
                #pragma unroll
                for (int nb = 0; nb < 4; ++nb) {
                    const float* a = acc3[mb * 4 + nb];
                    const int col = d0 + 8 * nb + cb;
                    *(float2*)(gO + (size_t)j * DD + col)       = make_float2(a[0], a[1]);
                    *(float2*)(gO + (size_t)(j + 8) * DD + col) = make_float2(a[2], a[3]);
                }
            }
        }
    }
}

extern "C" void kernel_launch(void* const* d_in, const int* in_sizes, int n_in,
                              void* d_out, int out_size)
{
    const float *X = nullptr, *A = nullptr, *W1 = nullptr, *b1 = nullptr,
                *W2 = nullptr, *b2 = nullptr;
    for (int idx = 0; idx < n_in; ++idx) {
        const float* p = (const float*)d_in[idx];
        int s = in_sizes[idx];
        if      (s == NB * NN * NN * DD) X = p;
        else if (s == NB * NN * NN)      A = p;
        else if (s == DD * DD)           { if (!W1) W1 = p; else W2 = p; }
        else if (s == DD)                { if (!b1) b1 = p; else b2 = p; }
    }

    prep_At<<<dim3(4, 4, 32), 256>>>(A);

    cudaFuncSetAttribute(crosssubg_mma_kernel,
                         cudaFuncAttributeMaxDynamicSharedMemorySize, SMEM_BYTES);
    crosssubg_mma_kernel<<<NCTA, 256, SMEM_BYTES>>>(X, W1, b1, W2, b2, (float*)d_out);
}